// round 4
// baseline (speedup 1.0000x reference)
#include <cuda_runtime.h>
#include <cuda_bf16.h>
#include <math.h>

// Problem constants
#define BATCH 2
#define SEQ 4096
#define DMODEL 512
#define NHEADS 8
#define HD 64
#define WINDOW 256
#define MROWS (BATCH * SEQ)       // 8192
#define QKV_N (3 * DMODEL)        // 1536

// Scratch buffers (device globals — no allocation allowed)
__device__ float g_qkv[MROWS * QKV_N];    // [8192, 1536]
__device__ float g_attn[MROWS * DMODEL];  // [8192, 512]

// ---------------------------------------------------------------------------
// NT SGEMM with bias: C[M,N] = A[M,K] @ B[N,K]^T + bias[N]
// Tiles: 64x64x16, 256 threads, 4x4 microtile per thread.
// M, N multiples of 64; K multiple of 16 (true for all our shapes).
// ---------------------------------------------------------------------------
#define TM 64
#define TN 64
#define TK 16

__global__ __launch_bounds__(256)
void sgemm_nt_bias(const float* __restrict__ A,
                   const float* __restrict__ Bw,
                   const float* __restrict__ bias,
                   float* __restrict__ C,
                   int M, int N, int K)
{
    __shared__ float As[TK][TM];
    __shared__ float Bs[TK][TN];

    const int tid = threadIdx.x;
    const int tx  = tid & 15;   // 0..15 -> n
    const int ty  = tid >> 4;   // 0..15 -> m
    const int m0  = blockIdx.y * TM;
    const int n0  = blockIdx.x * TN;

    // loader mapping: each thread loads one float4 of A and one of B per k-tile
    const int lr = tid >> 2;          // 0..63 (row within tile)
    const int lc = (tid & 3) * 4;     // 0,4,8,12 (k offset)

    float acc[4][4];
#pragma unroll
    for (int i = 0; i < 4; i++)
#pragma unroll
        for (int j = 0; j < 4; j++) acc[i][j] = 0.0f;

    const float* aptr = A  + (size_t)(m0 + lr) * K + lc;
    const float* bptr = Bw + (size_t)(n0 + lr) * K + lc;

    for (int k0 = 0; k0 < K; k0 += TK) {
        float4 a4 = *(const float4*)(aptr + k0);
        float4 b4 = *(const float4*)(bptr + k0);

        __syncthreads();   // previous tile fully consumed
        As[lc + 0][lr] = a4.x; As[lc + 1][lr] = a4.y;
        As[lc + 2][lr] = a4.z; As[lc + 3][lr] = a4.w;
        Bs[lc + 0][lr] = b4.x; Bs[lc + 1][lr] = b4.y;
        Bs[lc + 2][lr] = b4.z; Bs[lc + 3][lr] = b4.w;
        __syncthreads();

#pragma unroll
        for (int kk = 0; kk < TK; kk++) {
            float4 av = *(const float4*)&As[kk][ty * 4];
            float4 bv = *(const float4*)&Bs[kk][tx * 4];
            float a[4] = {av.x, av.y, av.z, av.w};
            float b[4] = {bv.x, bv.y, bv.z, bv.w};
#pragma unroll
            for (int i = 0; i < 4; i++)
#pragma unroll
                for (int j = 0; j < 4; j++)
                    acc[i][j] = fmaf(a[i], b[j], acc[i][j]);
        }
    }

    // epilogue: bias + vectorized store
    const int nc = n0 + tx * 4;
    float4 bv = *(const float4*)&bias[nc];
#pragma unroll
    for (int i = 0; i < 4; i++) {
        float4 r;
        r.x = acc[i][0] + bv.x;
        r.y = acc[i][1] + bv.y;
        r.z = acc[i][2] + bv.z;
        r.w = acc[i][3] + bv.w;
        *(float4*)&C[(size_t)(m0 + ty * 4 + i) * N + nc] = r;
    }
}

// ---------------------------------------------------------------------------
// Sliding-window attention (flash-style online softmax).
// Block: 256 threads = 8 warps; handles 32 queries of one (b, h).
// Each warp owns 4 queries. Lane = one key (score phase) / 2 dims (PV phase).
// K/V tiles (32x64) staged in SMEM with 68-float row stride (conflict-free
// for both LDS.128 per-lane-row reads and per-lane-column reads).
// ---------------------------------------------------------------------------
#define QT 32
#define KT 32
#define PAD 68

__global__ __launch_bounds__(256)
void attn_window_kernel(const float* __restrict__ qkv,
                        float* __restrict__ attn_out)
{
    __shared__ float Qs[QT][PAD];
    __shared__ float Ks[KT][PAD];
    __shared__ float Vs[KT][PAD];

    const int b     = blockIdx.z;
    const int h     = blockIdx.y;
    const int qbase = blockIdx.x * QT;
    const int tid   = threadIdx.x;
    const int warp  = tid >> 5;
    const int lane  = tid & 31;

    const float scale = 0.125f;  // 1/sqrt(64)

    // Load Q tile (coalesced over dims)
    for (int i = tid; i < QT * HD; i += 256) {
        int r = i >> 6, c = i & 63;
        Qs[r][c] = qkv[(size_t)(b * SEQ + qbase + r) * QKV_N + h * HD + c];
    }

    float o0[4], o1[4], m[4], l[4];
#pragma unroll
    for (int qi = 0; qi < 4; qi++) {
        o0[qi] = 0.f; o1[qi] = 0.f; m[qi] = -1e30f; l[qi] = 0.f;
    }

    int jstart = qbase - WINDOW;
    if (jstart < 0) jstart = 0;      // qbase multiple of 32 -> aligned
    const int jend = qbase + QT;

    for (int j0 = jstart; j0 < jend; j0 += KT) {
        __syncthreads();   // previous tile fully consumed
        for (int i = tid; i < KT * HD; i += 256) {
            int r = i >> 6, c = i & 63;
            size_t base = (size_t)(b * SEQ + j0 + r) * QKV_N + h * HD;
            Ks[r][c] = qkv[base + DMODEL + c];          // K
            Vs[r][c] = qkv[base + 2 * DMODEL + c];      // V
        }
        __syncthreads();

#pragma unroll
        for (int qi = 0; qi < 4; qi++) {
            const int qrow = warp * 4 + qi;
            const int q    = qbase + qrow;

            // score for key (j0 + lane): dot over 64 dims, float4 steps
            const float4* qp = (const float4*)&Qs[qrow][0];
            const float4* kp = (const float4*)&Ks[lane][0];
            float s = 0.f;
#pragma unroll
            for (int d4 = 0; d4 < 16; d4++) {
                float4 qv = qp[d4];
                float4 kv = kp[d4];
                s = fmaf(qv.x, kv.x, s);
                s = fmaf(qv.y, kv.y, s);
                s = fmaf(qv.z, kv.z, s);
                s = fmaf(qv.w, kv.w, s);
            }
            s *= scale;

            const int j = j0 + lane;
            const bool valid = (j <= q) && (j >= q - WINDOW);
            s = valid ? s : -1e30f;

            // warp-wide max
            float mc = s;
#pragma unroll
            for (int o = 16; o; o >>= 1)
                mc = fmaxf(mc, __shfl_xor_sync(0xffffffffu, mc, o));
            const float mnew  = fmaxf(m[qi], mc);
            const float p     = __expf(s - mnew);
            const float alpha = __expf(m[qi] - mnew);
            m[qi] = mnew;

            float ps = p;
#pragma unroll
            for (int o = 16; o; o >>= 1)
                ps += __shfl_xor_sync(0xffffffffu, ps, o);
            l[qi] = l[qi] * alpha + ps;

            float a0 = o0[qi] * alpha;
            float a1 = o1[qi] * alpha;
#pragma unroll
            for (int jj = 0; jj < KT; jj++) {
                float pj = __shfl_sync(0xffffffffu, p, jj);
                a0 = fmaf(pj, Vs[jj][lane],      a0);
                a1 = fmaf(pj, Vs[jj][lane + 32], a1);
            }
            o0[qi] = a0;
            o1[qi] = a1;
        }
    }

    // write: attn_out[(b,q), h*64 + {lane, lane+32}]
#pragma unroll
    for (int qi = 0; qi < 4; qi++) {
        const int q = qbase + warp * 4 + qi;
        const float inv = 1.0f / l[qi];
        float* dst = &attn_out[(size_t)(b * SEQ + q) * DMODEL + h * HD];
        dst[lane]      = o0[qi] * inv;
        dst[lane + 32] = o1[qi] * inv;
    }
}

// ---------------------------------------------------------------------------
// kernel_launch
// Inputs (metadata order): x, qkv_w, qkv_b, out_w, out_b — all float32.
// Output: float32 [2, 4096, 512].
// ---------------------------------------------------------------------------
extern "C" void kernel_launch(void* const* d_in, const int* in_sizes, int n_in,
                              void* d_out, int out_size)
{
    const float* x     = (const float*)d_in[0];
    const float* qkv_w = (const float*)d_in[1];
    const float* qkv_b = (const float*)d_in[2];
    const float* out_w = (const float*)d_in[3];
    const float* out_b = (const float*)d_in[4];
    float* out = (float*)d_out;

    float* qkv_buf;  cudaGetSymbolAddress((void**)&qkv_buf,  g_qkv);
    float* attn_buf; cudaGetSymbolAddress((void**)&attn_buf, g_attn);

    // 1) QKV projection: [8192,512] @ [512,1536] + bias
    {
        dim3 grid(QKV_N / TN, MROWS / TM);
        sgemm_nt_bias<<<grid, 256>>>(x, qkv_w, qkv_b, qkv_buf,
                                     MROWS, QKV_N, DMODEL);
    }

    // 2) Sliding-window attention
    {
        dim3 grid(SEQ / QT, NHEADS, BATCH);
        attn_window_kernel<<<grid, 256>>>(qkv_buf, attn_buf);
    }

    // 3) Output projection: [8192,512] @ [512,512] + bias
    {
        dim3 grid(DMODEL / TN, MROWS / TM);
        sgemm_nt_bias<<<grid, 256>>>(attn_buf, out_w, out_b, out,
                                     MROWS, DMODEL, DMODEL);
    }
}

// round 5
// speedup vs baseline: 1.5140x; 1.5140x over previous
#include <cuda_runtime.h>
#include <cuda_bf16.h>
#include <math.h>

// Problem constants
#define BATCH 2
#define SEQ 4096
#define DMODEL 512
#define NHEADS 8
#define HD 64
#define WINDOW 256
#define MROWS (BATCH * SEQ)       // 8192
#define QKV_N (3 * DMODEL)        // 1536

// Scratch buffers (device globals — no allocation allowed)
__device__ float g_qkv[MROWS * QKV_N];    // [8192, 1536]
__device__ float g_attn[MROWS * DMODEL];  // [8192, 512]

// ---------------------------------------------------------------------------
// NT SGEMM with bias: C[M,N] = A[M,K] @ B[N,K]^T + bias[N]
// Tiles: 128x128x8, 256 threads, 8x8 microtile, register prefetch.
// M, N multiples of 128; K multiple of 8.
// ---------------------------------------------------------------------------
#define GTM 128
#define GTN 128
#define GTK 8
#define GPAD 132   // +4 padding: conflict-free transpose stores

__global__ __launch_bounds__(256, 2)
void sgemm_nt_bias(const float* __restrict__ A,
                   const float* __restrict__ Bw,
                   const float* __restrict__ bias,
                   float* __restrict__ C,
                   int M, int N, int K)
{
    __shared__ float As[GTK][GPAD];
    __shared__ float Bs[GTK][GPAD];

    const int tid = threadIdx.x;
    const int tx  = tid & 15;   // n quadrant index
    const int ty  = tid >> 4;   // m quadrant index
    const int m0  = blockIdx.y * GTM;
    const int n0  = blockIdx.x * GTN;

    // loaders: each thread loads one float4 of A and one of B per k-slab
    const int lr = tid >> 1;         // 0..127 row within tile
    const int lc = (tid & 1) * 4;    // 0 or 4 (k offset)

    const float* aptr = A  + (size_t)(m0 + lr) * K + lc;
    const float* bptr = Bw + (size_t)(n0 + lr) * K + lc;

    float acc[8][8];
#pragma unroll
    for (int i = 0; i < 8; i++)
#pragma unroll
        for (int j = 0; j < 8; j++) acc[i][j] = 0.0f;

    float4 a4 = *(const float4*)aptr;
    float4 b4 = *(const float4*)bptr;

    for (int k0 = 0; k0 < K; k0 += GTK) {
        __syncthreads();   // previous slab fully consumed
        As[lc + 0][lr] = a4.x; As[lc + 1][lr] = a4.y;
        As[lc + 2][lr] = a4.z; As[lc + 3][lr] = a4.w;
        Bs[lc + 0][lr] = b4.x; Bs[lc + 1][lr] = b4.y;
        Bs[lc + 2][lr] = b4.z; Bs[lc + 3][lr] = b4.w;
        __syncthreads();

        if (k0 + GTK < K) {
            a4 = *(const float4*)(aptr + k0 + GTK);
            b4 = *(const float4*)(bptr + k0 + GTK);
        }

#pragma unroll
        for (int kk = 0; kk < GTK; kk++) {
            float4 av0 = *(const float4*)&As[kk][ty * 4];
            float4 av1 = *(const float4*)&As[kk][ty * 4 + 64];
            float4 bv0 = *(const float4*)&Bs[kk][tx * 4];
            float4 bv1 = *(const float4*)&Bs[kk][tx * 4 + 64];
            float a[8] = {av0.x, av0.y, av0.z, av0.w, av1.x, av1.y, av1.z, av1.w};
            float b[8] = {bv0.x, bv0.y, bv0.z, bv0.w, bv1.x, bv1.y, bv1.z, bv1.w};
#pragma unroll
            for (int i = 0; i < 8; i++)
#pragma unroll
                for (int j = 0; j < 8; j++)
                    acc[i][j] = fmaf(a[i], b[j], acc[i][j]);
        }
    }

    // epilogue: bias + vectorized stores (two 4-wide column groups)
    const int nc0 = n0 + tx * 4;
    float4 biv0 = *(const float4*)&bias[nc0];
    float4 biv1 = *(const float4*)&bias[nc0 + 64];
#pragma unroll
    for (int i = 0; i < 8; i++) {
        const int row = m0 + ((i < 4) ? (ty * 4 + i) : (64 + ty * 4 + (i - 4)));
        float4 r0, r1;
        r0.x = acc[i][0] + biv0.x; r0.y = acc[i][1] + biv0.y;
        r0.z = acc[i][2] + biv0.z; r0.w = acc[i][3] + biv0.w;
        r1.x = acc[i][4] + biv1.x; r1.y = acc[i][5] + biv1.y;
        r1.z = acc[i][6] + biv1.z; r1.w = acc[i][7] + biv1.w;
        *(float4*)&C[(size_t)row * N + nc0]      = r0;
        *(float4*)&C[(size_t)row * N + nc0 + 64] = r1;
    }
}

// ---------------------------------------------------------------------------
// Sliding-window attention (flash-style online softmax), restructured:
//  - score phase: lane = key, 4 query accumulators per lane (K read ONCE per
//    warp-tile; Q reads are broadcasts)
//  - PV phase: p staged in SMEM, lane = dim pair, V float2 shared across the
//    4 queries, p read as broadcast float4 (no shuffles, no scalar LDS)
// Block: 256 threads = 8 warps; 32 queries of one (b, h) per block.
// ---------------------------------------------------------------------------
#define QT 32
#define KT 32
#define PAD 68

__global__ __launch_bounds__(256)
void attn_window_kernel(const float* __restrict__ qkv,
                        float* __restrict__ attn_out)
{
    __shared__ float Qs[QT][PAD];
    __shared__ float Ks[KT][PAD];
    __shared__ float Vs[KT][PAD];
    __shared__ float Ps[8][4][KT];   // [warp][qi][key]

    const int b     = blockIdx.z;
    const int h     = blockIdx.y;
    const int qbase = blockIdx.x * QT;
    const int tid   = threadIdx.x;
    const int warp  = tid >> 5;
    const int lane  = tid & 31;

    const float scale = 0.125f;  // 1/sqrt(64)

    // Load Q tile (vectorized, coalesced over dims)
    for (int i = tid; i < QT * HD / 4; i += 256) {
        int r = i >> 4, c = (i & 15) * 4;
        float4 v = *(const float4*)&qkv[(size_t)(b * SEQ + qbase + r) * QKV_N + h * HD + c];
        *(float4*)&Qs[r][c] = v;
    }

    float ox[4], oy[4], m[4], l[4];
#pragma unroll
    for (int qi = 0; qi < 4; qi++) {
        ox[qi] = 0.f; oy[qi] = 0.f; m[qi] = -1e30f; l[qi] = 0.f;
    }

    int jstart = qbase - WINDOW;
    if (jstart < 0) jstart = 0;      // qbase multiple of 32 -> stays aligned
    const int jend = qbase + QT;
    const int qr = warp * 4;

    for (int j0 = jstart; j0 < jend; j0 += KT) {
        __syncthreads();   // previous tile fully consumed
        for (int i = tid; i < KT * HD / 4; i += 256) {
            int r = i >> 4, c = (i & 15) * 4;
            size_t base = (size_t)(b * SEQ + j0 + r) * QKV_N + h * HD + c;
            float4 kv = *(const float4*)&qkv[base + DMODEL];
            float4 vv = *(const float4*)&qkv[base + 2 * DMODEL];
            *(float4*)&Ks[r][c] = kv;
            *(float4*)&Vs[r][c] = vv;
        }
        __syncthreads();

        // ---- score phase: lane = key (j0+lane), 4 queries at once ----
        float s[4] = {0.f, 0.f, 0.f, 0.f};
        const float4* kp = (const float4*)&Ks[lane][0];
#pragma unroll
        for (int d4 = 0; d4 < 16; d4++) {
            float4 kv = kp[d4];
            float4 q0 = *(const float4*)&Qs[qr + 0][d4 * 4];
            float4 q1 = *(const float4*)&Qs[qr + 1][d4 * 4];
            float4 q2 = *(const float4*)&Qs[qr + 2][d4 * 4];
            float4 q3 = *(const float4*)&Qs[qr + 3][d4 * 4];
            s[0] = fmaf(kv.x, q0.x, s[0]); s[0] = fmaf(kv.y, q0.y, s[0]);
            s[0] = fmaf(kv.z, q0.z, s[0]); s[0] = fmaf(kv.w, q0.w, s[0]);
            s[1] = fmaf(kv.x, q1.x, s[1]); s[1] = fmaf(kv.y, q1.y, s[1]);
            s[1] = fmaf(kv.z, q1.z, s[1]); s[1] = fmaf(kv.w, q1.w, s[1]);
            s[2] = fmaf(kv.x, q2.x, s[2]); s[2] = fmaf(kv.y, q2.y, s[2]);
            s[2] = fmaf(kv.z, q2.z, s[2]); s[2] = fmaf(kv.w, q2.w, s[2]);
            s[3] = fmaf(kv.x, q3.x, s[3]); s[3] = fmaf(kv.y, q3.y, s[3]);
            s[3] = fmaf(kv.z, q3.z, s[3]); s[3] = fmaf(kv.w, q3.w, s[3]);
        }

        const int j = j0 + lane;
#pragma unroll
        for (int qi = 0; qi < 4; qi++) {
            const int q = qbase + qr + qi;
            float sv = s[qi] * scale;
            const bool valid = (j <= q) && (j >= q - WINDOW);
            sv = valid ? sv : -1e30f;

            float mc = sv;
#pragma unroll
            for (int o = 16; o; o >>= 1)
                mc = fmaxf(mc, __shfl_xor_sync(0xffffffffu, mc, o));
            const float mnew  = fmaxf(m[qi], mc);
            const float p     = __expf(sv - mnew);
            const float alpha = __expf(m[qi] - mnew);
            m[qi] = mnew;

            float ps = p;
#pragma unroll
            for (int o = 16; o; o >>= 1)
                ps += __shfl_xor_sync(0xffffffffu, ps, o);
            l[qi]  = l[qi] * alpha + ps;
            ox[qi] *= alpha;
            oy[qi] *= alpha;
            Ps[warp][qi][lane] = p;
        }
        __syncwarp();

        // ---- PV phase: lane = dim pair (2*lane, 2*lane+1) ----
#pragma unroll
        for (int jj = 0; jj < KT; jj += 4) {
            float2 v0 = *(const float2*)&Vs[jj + 0][lane * 2];
            float2 v1 = *(const float2*)&Vs[jj + 1][lane * 2];
            float2 v2 = *(const float2*)&Vs[jj + 2][lane * 2];
            float2 v3 = *(const float2*)&Vs[jj + 3][lane * 2];
#pragma unroll
            for (int qi = 0; qi < 4; qi++) {
                float4 p4 = *(const float4*)&Ps[warp][qi][jj];
                ox[qi] = fmaf(p4.x, v0.x, ox[qi]);
                ox[qi] = fmaf(p4.y, v1.x, ox[qi]);
                ox[qi] = fmaf(p4.z, v2.x, ox[qi]);
                ox[qi] = fmaf(p4.w, v3.x, ox[qi]);
                oy[qi] = fmaf(p4.x, v0.y, oy[qi]);
                oy[qi] = fmaf(p4.y, v1.y, oy[qi]);
                oy[qi] = fmaf(p4.z, v2.y, oy[qi]);
                oy[qi] = fmaf(p4.w, v3.y, oy[qi]);
            }
        }
    }

    // write: attn_out[(b,q), h*64 + {2*lane, 2*lane+1}]
#pragma unroll
    for (int qi = 0; qi < 4; qi++) {
        const int q = qbase + qr + qi;
        const float inv = 1.0f / l[qi];
        float2 r;
        r.x = ox[qi] * inv;
        r.y = oy[qi] * inv;
        *(float2*)&attn_out[(size_t)(b * SEQ + q) * DMODEL + h * HD + lane * 2] = r;
    }
}

// ---------------------------------------------------------------------------
// kernel_launch
// Inputs (metadata order): x, qkv_w, qkv_b, out_w, out_b — all float32.
// Output: float32 [2, 4096, 512].
// ---------------------------------------------------------------------------
extern "C" void kernel_launch(void* const* d_in, const int* in_sizes, int n_in,
                              void* d_out, int out_size)
{
    const float* x     = (const float*)d_in[0];
    const float* qkv_w = (const float*)d_in[1];
    const float* qkv_b = (const float*)d_in[2];
    const float* out_w = (const float*)d_in[3];
    const float* out_b = (const float*)d_in[4];
    float* out = (float*)d_out;

    float* qkv_buf;  cudaGetSymbolAddress((void**)&qkv_buf,  g_qkv);
    float* attn_buf; cudaGetSymbolAddress((void**)&attn_buf, g_attn);

    // 1) QKV projection: [8192,512] @ [512,1536] + bias
    {
        dim3 grid(QKV_N / GTN, MROWS / GTM);
        sgemm_nt_bias<<<grid, 256>>>(x, qkv_w, qkv_b, qkv_buf,
                                     MROWS, QKV_N, DMODEL);
    }

    // 2) Sliding-window attention
    {
        dim3 grid(SEQ / QT, NHEADS, BATCH);
        attn_window_kernel<<<grid, 256>>>(qkv_buf, attn_buf);
    }

    // 3) Output projection: [8192,512] @ [512,512] + bias
    {
        dim3 grid(DMODEL / GTN, MROWS / GTM);
        sgemm_nt_bias<<<grid, 256>>>(attn_buf, out_w, out_b, out,
                                     MROWS, DMODEL, DMODEL);
    }
}